// round 10
// baseline (speedup 1.0000x reference)
#include <cuda_runtime.h>
#include <cuda_fp16.h>
#include <mma.h>
#include <cstdint>

using namespace nvcuda;

// ---------------- problem constants ----------------
#define K_DIM 4096
#define N_DIM 11008
#define M_DIM 8192

// ---------------- tiling ----------------
#define BM 256
#define BN 128
#define BK 64
#define KT (K_DIM / BK)      // 64
#define NTHREADS 256         // 8 warps, 4x2 grid of 64x64 warp tiles
#define LDT 72               // padded smem stride in halves (144B rows)

// smem byte offsets (dynamic): 4 A buffers, 2 B buffers
#define A_BYTES (BM * LDT * 2)      // 36864
#define B_BYTES (BN * LDT * 2)      // 18432
#define OFF_A0 0
#define OFF_A1 (1 * A_BYTES)
#define OFF_A2 (2 * A_BYTES)
#define OFF_A3 (3 * A_BYTES)
#define OFF_B0 (4 * A_BYTES)
#define OFF_B1 (4 * A_BYTES + B_BYTES)
#define SMEM_TOTAL (4 * A_BYTES + 2 * B_BYTES)   // 184320 -> 1 CTA/SM

// fp16 copy of x with k-permutation [0,4,1,5,2,6,3,7] within each 8-group
// (fp32 inputs are exact fp16 values -> lossless)
__device__ __half g_xh[(size_t)M_DIM * K_DIM];

__device__ __forceinline__ uint32_t smem_u32(const void* p) {
    uint32_t a;
    asm("{ .reg .u64 t; cvta.to.shared.u64 t, %1; cvt.u32.u64 %0, t; }" : "=r"(a) : "l"(p));
    return a;
}
__device__ __forceinline__ void cp_async16(uint32_t dst, const void* src) {
    asm volatile("cp.async.cg.shared.global [%0], [%1], 16;" :: "r"(dst), "l"(src) : "memory");
}
__device__ __forceinline__ void cp_commit() {
    asm volatile("cp.async.commit_group;" ::: "memory");
}
__device__ __forceinline__ void cp_wait0() {
    asm volatile("cp.async.wait_group 0;" ::: "memory");
}
__device__ __forceinline__ void cp_wait1() {
    asm volatile("cp.async.wait_group 1;" ::: "memory");
}
__device__ __forceinline__ void cp_wait2() {
    asm volatile("cp.async.wait_group 2;" ::: "memory");
}

// ---------------- pre-pass: x fp32 -> fp16, k-pair-permuted ----------------
// output order per 8-group: (f0,f4),(f1,f5),(f2,f6),(f3,f7)
__global__ __launch_bounds__(256) void convert_x_kernel(const float* __restrict__ x) {
    size_t i = (size_t)blockIdx.x * 256 + threadIdx.x;   // one uint4 (8 halves) per thread
    const float4* p = reinterpret_cast<const float4*>(x) + 2 * i;
    float4 a = p[0], b = p[1];   // a = k0..k3, b = k4..k7
    __half2 h[4];
    h[0] = __floats2half2_rn(a.x, b.x);   // (k0, k4)
    h[1] = __floats2half2_rn(a.y, b.y);   // (k1, k5)
    h[2] = __floats2half2_rn(a.z, b.z);   // (k2, k6)
    h[3] = __floats2half2_rn(a.w, b.w);   // (k3, k7)
    reinterpret_cast<uint4*>(g_xh)[i] = *reinterpret_cast<uint4*>(h);
}

// ---------------- main fused dequant-GEMM ----------------
__global__ __launch_bounds__(NTHREADS, 1)
void gptq_gemm_kernel(const int*   __restrict__ qw,
                      const float* __restrict__ scales,
                      const float* __restrict__ bias,
                      float*       __restrict__ out)
{
    extern __shared__ __align__(128) char smem[];
    const uint32_t sb = smem_u32(smem);

    const int tid     = threadIdx.x;
    const int warp_id = tid >> 5;
    const int lane    = tid & 31;
    const int m0 = blockIdx.y * BM;
    const int n0 = blockIdx.x * BN;

    // warp grid: 4 along M x 2 along N, each warp owns 64x64
    const int wm = warp_id & 3;
    const int wn = warp_id >> 2;

    wmma::fragment<wmma::accumulator, 16, 16, 16, float> cf[4][4];
    #pragma unroll
    for (int i = 0; i < 4; i++)
        #pragma unroll
        for (int j = 0; j < 4; j++)
            wmma::fill_fragment(cf[i][j], 0.0f);

    // ---- B register prefetch state ----
    // 256 threads cover 128 n-cols x 2 kq-halves: n = tid&127, h = tid>>7
    // each thread owns 4 packed words (kq = 4h + 0..3) per tile
    int     wreg[4];
    __half2 s2;
    const int n = tid & 127;
    const int h = tid >> 7;

    auto ldgB = [&](int kt) {
        const int k0 = kt * BK;
        float sf = scales[(size_t)(k0 >> 7) * N_DIM + n0 + n];
        s2 = __half2half2(__float2half(sf));
        const int* qp = qw + (size_t)((k0 >> 3) + 4 * h) * N_DIM + n0 + n;
        #pragma unroll
        for (int r = 0; r < 4; r++)
            wreg[r] = qp[(size_t)r * N_DIM];
    };

    auto cpA = [&](int kt, uint32_t a_off) {
        const int k0 = kt * BK;
        #pragma unroll
        for (int r = 0; r < 8; r++) {
            int idx = tid + NTHREADS * r;          // 0..2047
            int row = idx >> 3, c = idx & 7;
            cp_async16(sb + a_off + (uint32_t)(row * (LDT * 2) + c * 16),
                       g_xh + (size_t)(m0 + row) * K_DIM + k0 + c * 8);
        }
        cp_commit();
    };

    const __half2 c1032 = __floats2half2_rn(1032.0f, 1032.0f);
    const uint32_t a_offs[4] = {OFF_A0, OFF_A1, OFF_A2, OFF_A3};

    // ---- prologue: A(0..2) in flight; B(0) words in regs ----
    cpA(0, OFF_A0);
    cpA(1, OFF_A1);
    cpA(2, OFF_A2);
    ldgB(0);

    for (int kt = 0; kt < KT; kt++) {
        const uint32_t a_off = a_offs[kt & 3];
        const uint32_t b_off = (kt & 1) ? OFF_B1 : OFF_B0;

        // ---- dequant B(kt) regs -> smem (bulk phase, nibble-pair form) ----
        #pragma unroll
        for (int r = 0; r < 4; r++) {
            unsigned q = (unsigned)wreg[r];
            unsigned y0 = (q         & 0x000f000fu) | 0x64006400u;  // (k0,k4)+1024
            unsigned y1 = ((q >> 4)  & 0x000f000fu) | 0x64006400u;  // (k1,k5)+1024
            unsigned y2 = ((q >> 8)  & 0x000f000fu) | 0x64006400u;  // (k2,k6)+1024
            unsigned y3 = ((q >> 12) & 0x000f000fu) | 0x64006400u;  // (k3,k7)+1024
            __half2 v[4];
            v[0] = __hmul2(__hsub2(*reinterpret_cast<__half2*>(&y0), c1032), s2);
            v[1] = __hmul2(__hsub2(*reinterpret_cast<__half2*>(&y1), c1032), s2);
            v[2] = __hmul2(__hsub2(*reinterpret_cast<__half2*>(&y2), c1032), s2);
            v[3] = __hmul2(__hsub2(*reinterpret_cast<__half2*>(&y3), c1032), s2);
            *reinterpret_cast<uint4*>(smem + b_off + n * (LDT * 2) + (4 * h + r) * 16) =
                *reinterpret_cast<uint4*>(v);
        }

        // A(kt) resident: exact tail laddering of outstanding groups
        if (kt < KT - 2)       cp_wait2();
        else if (kt == KT - 2) cp_wait1();
        else                   cp_wait0();
        __syncthreads();     // (A,B)(kt) visible; all warps done with old buffers

        // ---- prefetch: A three ahead, B one ahead (overlap with MMA below) ----
        if (kt + 3 < KT) cpA(kt + 3, a_offs[(kt + 3) & 3]);
        if (kt + 1 < KT) ldgB(kt + 1);

        // ---- pure tensor phase on smem tiles ----
        const __half* As = reinterpret_cast<const __half*>(smem + a_off);
        const __half* Bs = reinterpret_cast<const __half*>(smem + b_off);
        #pragma unroll
        for (int ks = 0; ks < BK / 16; ks++) {
            wmma::fragment<wmma::matrix_a, 16, 16, 16, __half, wmma::row_major> af[4];
            wmma::fragment<wmma::matrix_b, 16, 16, 16, __half, wmma::col_major> bf[4];
            #pragma unroll
            for (int i = 0; i < 4; i++)
                wmma::load_matrix_sync(af[i], As + (wm * 64 + i * 16) * LDT + ks * 16, LDT);
            #pragma unroll
            for (int j = 0; j < 4; j++)
                wmma::load_matrix_sync(bf[j], Bs + (wn * 64 + j * 16) * LDT + ks * 16, LDT);
            #pragma unroll
            for (int i = 0; i < 4; i++)
                #pragma unroll
                for (int j = 0; j < 4; j++)
                    wmma::mma_sync(cf[i][j], af[i], bf[j], cf[i][j]);
        }
    }

    // ---- epilogue: strip-staged, coalesced, fused bias ----
    __syncthreads();   // everyone done with smem tiles; reuse as staging
    float* stage = reinterpret_cast<float*>(smem) + warp_id * (17 * 64);

    const int row0 = m0 + wm * 64;
    const int col0 = n0 + wn * 64;

    #pragma unroll
    for (int i = 0; i < 4; i++) {
        #pragma unroll
        for (int j = 0; j < 4; j++)
            wmma::store_matrix_sync(stage + j * 16, cf[i][j], 68, wmma::mem_row_major);
        __syncwarp();
        #pragma unroll
        for (int q = 0; q < 8; q++) {
            int idx = q * 32 + lane;       // 0..255 float4s
            int r  = idx >> 4;
            int c4 = idx & 15;
            float4 v = *reinterpret_cast<const float4*>(stage + r * 68 + c4 * 4);
            const float4 bb = *reinterpret_cast<const float4*>(bias + col0 + c4 * 4);
            v.x += bb.x; v.y += bb.y; v.z += bb.z; v.w += bb.w;
            *reinterpret_cast<float4*>(
                out + (size_t)(row0 + i * 16 + r) * N_DIM + col0 + c4 * 4) = v;
        }
        __syncwarp();
    }
}

extern "C" void kernel_launch(void* const* d_in, const int* in_sizes, int n_in,
                              void* d_out, int out_size)
{
    const float* x      = (const float*)d_in[0];
    const int*   qw     = (const int*)d_in[1];
    const float* scales = (const float*)d_in[2];
    const float* bias   = (const float*)d_in[3];
    float* out = (float*)d_out;

    cudaFuncSetAttribute(gptq_gemm_kernel,
                         cudaFuncAttributeMaxDynamicSharedMemorySize, SMEM_TOTAL);

    // pre-pass: fp32 -> fp16 permuted (8 halves per thread)
    convert_x_kernel<<<(M_DIM * K_DIM) / 8 / 256, 256>>>(x);

    dim3 grid(N_DIM / BN, M_DIM / BM);   // (86, 32)
    gptq_gemm_kernel<<<grid, NTHREADS, SMEM_TOTAL>>>(qw, scales, bias, out);
}

// round 12
// speedup vs baseline: 1.0370x; 1.0370x over previous
#include <cuda_runtime.h>
#include <cuda_fp16.h>
#include <mma.h>
#include <cstdint>

using namespace nvcuda;

// ---------------- problem constants ----------------
#define K_DIM 4096
#define N_DIM 11008
#define M_DIM 8192

// ---------------- tiling ----------------
#define BM 128
#define BN 128
#define BK 64
#define KT (K_DIM / BK)      // 64
#define NTHREADS 128         // 4 warps, 2x2 grid of 64x64 warp tiles
#define LDT 72               // padded smem stride in halves (144B rows)

// smem: 3 A buffers + 3 B buffers (triple-buffered, depth-2 in flight)
#define A_BYTES (BM * LDT * 2)      // 18432
#define B_BYTES (BN * LDT * 2)      // 18432
#define SMEM_TOTAL (3 * A_BYTES + 3 * B_BYTES)   // 110592 -> 2 CTAs/SM

// fp16 scratch, both with k-pair permutation [0,4,1,5,2,6,3,7] per 8-group
// (consistent permutation of both operands leaves the GEMM invariant;
//  fp32 x values are exact fp16 -> lossless)
__device__ __half g_xh[(size_t)M_DIM * K_DIM];
__device__ __half g_wh[(size_t)N_DIM * K_DIM];   // [N][K]

__device__ __forceinline__ uint32_t smem_u32(const void* p) {
    uint32_t a;
    asm("{ .reg .u64 t; cvta.to.shared.u64 t, %1; cvt.u32.u64 %0, t; }" : "=r"(a) : "l"(p));
    return a;
}
__device__ __forceinline__ void cp_async16(uint32_t dst, const void* src) {
    asm volatile("cp.async.cg.shared.global [%0], [%1], 16;" :: "r"(dst), "l"(src) : "memory");
}
__device__ __forceinline__ void cp_commit() {
    asm volatile("cp.async.commit_group;" ::: "memory");
}
__device__ __forceinline__ void cp_wait0() {
    asm volatile("cp.async.wait_group 0;" ::: "memory");
}
__device__ __forceinline__ void cp_wait1() {
    asm volatile("cp.async.wait_group 1;" ::: "memory");
}

// ---------------- pre-pass 1: x fp32 -> fp16, k-pair-permuted ----------------
// output order per 8-group: (f0,f4),(f1,f5),(f2,f6),(f3,f7)
__global__ __launch_bounds__(256) void convert_x_kernel(const float* __restrict__ x) {
    size_t i = (size_t)blockIdx.x * 256 + threadIdx.x;   // one uint4 (8 halves) per thread
    const float4* p = reinterpret_cast<const float4*>(x) + 2 * i;
    float4 a = p[0], b = p[1];   // a = k0..k3, b = k4..k7
    __half2 h[4];
    h[0] = __floats2half2_rn(a.x, b.x);
    h[1] = __floats2half2_rn(a.y, b.y);
    h[2] = __floats2half2_rn(a.z, b.z);
    h[3] = __floats2half2_rn(a.w, b.w);
    reinterpret_cast<uint4*>(g_xh)[i] = *reinterpret_cast<uint4*>(h);
}

// ---------------- pre-pass 2: dequant W -> fp16 [N][K], permuted ----------------
// grid (K/64, N/256), 256 threads; thread owns one n-column, 8 packed words
__global__ __launch_bounds__(256) void dequant_w_kernel(
    const int* __restrict__ qw, const float* __restrict__ scales)
{
    const int k0 = blockIdx.x * 64;
    const int n  = blockIdx.y * 256 + threadIdx.x;

    float sf = scales[(size_t)(k0 >> 7) * N_DIM + n];
    __half2 s2 = __half2half2(__float2half(sf));
    const __half2 c1032 = __floats2half2_rn(1032.0f, 1032.0f);

    const int* qp = qw + (size_t)(k0 >> 3) * N_DIM + n;
    uint4* wp = reinterpret_cast<uint4*>(g_wh + (size_t)n * K_DIM + k0);

    #pragma unroll
    for (int r = 0; r < 8; r++) {
        unsigned q = (unsigned)qp[(size_t)r * N_DIM];
        unsigned y0 = (q         & 0x000f000fu) | 0x64006400u;  // (k0,k4)+1024
        unsigned y1 = ((q >> 4)  & 0x000f000fu) | 0x64006400u;  // (k1,k5)+1024
        unsigned y2 = ((q >> 8)  & 0x000f000fu) | 0x64006400u;  // (k2,k6)+1024
        unsigned y3 = ((q >> 12) & 0x000f000fu) | 0x64006400u;  // (k3,k7)+1024
        __half2 v[4];
        v[0] = __hmul2(__hsub2(*reinterpret_cast<__half2*>(&y0), c1032), s2);
        v[1] = __hmul2(__hsub2(*reinterpret_cast<__half2*>(&y1), c1032), s2);
        v[2] = __hmul2(__hsub2(*reinterpret_cast<__half2*>(&y2), c1032), s2);
        v[3] = __hmul2(__hsub2(*reinterpret_cast<__half2*>(&y3), c1032), s2);
        wp[r] = *reinterpret_cast<uint4*>(v);   // 16B; thread writes 128B contiguous
    }
}

// ---------------- main GEMM (pure fp16, cp.async both operands) ----------------
__global__ __launch_bounds__(NTHREADS, 2)
void gptq_gemm_kernel(const float* __restrict__ bias,
                      float*       __restrict__ out)
{
    extern __shared__ __align__(128) char smem[];
    const uint32_t sb = smem_u32(smem);

    const int tid     = threadIdx.x;
    const int warp_id = tid >> 5;
    const int lane    = tid & 31;
    const int m0 = blockIdx.y * BM;
    const int n0 = blockIdx.x * BN;

    // warp grid: 2 along M x 2 along N, each warp owns 64x64
    const int wm = warp_id & 1;
    const int wn = warp_id >> 1;

    wmma::fragment<wmma::accumulator, 16, 16, 16, float> cf[4][4];
    #pragma unroll
    for (int i = 0; i < 4; i++)
        #pragma unroll
        for (int j = 0; j < 4; j++)
            wmma::fill_fragment(cf[i][j], 0.0f);

    // issue one combined A+B tile copy (one commit group)
    auto cpAB = [&](int kt, int bufidx) {
        const int k0 = kt * BK;
        const uint32_t a_off = (uint32_t)(bufidx * A_BYTES);
        const uint32_t b_off = (uint32_t)(3 * A_BYTES + bufidx * B_BYTES);
        #pragma unroll
        for (int r = 0; r < 8; r++) {
            int idx = tid + NTHREADS * r;          // 0..1023
            int row = idx >> 3, c = idx & 7;
            cp_async16(sb + a_off + (uint32_t)(row * (LDT * 2) + c * 16),
                       g_xh + (size_t)(m0 + row) * K_DIM + k0 + c * 8);
        }
        #pragma unroll
        for (int r = 0; r < 8; r++) {
            int idx = tid + NTHREADS * r;          // 0..1023
            int row = idx >> 3, c = idx & 7;
            cp_async16(sb + b_off + (uint32_t)(row * (LDT * 2) + c * 16),
                       g_wh + (size_t)(n0 + row) * K_DIM + k0 + c * 8);
        }
        cp_commit();
    };

    // ---- prologue: tiles 0,1 in flight ----
    cpAB(0, 0);
    cpAB(1, 1);

    int bufidx = 0;  // kt % 3

    for (int kt = 0; kt < KT; kt++) {
        const uint32_t a_off = (uint32_t)(bufidx * A_BYTES);
        const uint32_t b_off = (uint32_t)(3 * A_BYTES + bufidx * B_BYTES);

        // tile kt resident (kt+1 may remain in flight)
        if (kt < KT - 1) cp_wait1(); else cp_wait0();
        __syncthreads();     // all warps done with MMA(kt-1) -> buffer (kt+2)%3 free

        if (kt + 2 < KT) {
            int nxt = bufidx + 2; if (nxt >= 3) nxt -= 3;
            cpAB(kt + 2, nxt);
        }

        // ---- pure tensor phase ----
        const __half* As = reinterpret_cast<const __half*>(smem + a_off);
        const __half* Bs = reinterpret_cast<const __half*>(smem + b_off);
        #pragma unroll
        for (int ks = 0; ks < BK / 16; ks++) {
            wmma::fragment<wmma::matrix_a, 16, 16, 16, __half, wmma::row_major> af[4];
            wmma::fragment<wmma::matrix_b, 16, 16, 16, __half, wmma::col_major> bf[4];
            #pragma unroll
            for (int i = 0; i < 4; i++)
                wmma::load_matrix_sync(af[i], As + (wm * 64 + i * 16) * LDT + ks * 16, LDT);
            #pragma unroll
            for (int j = 0; j < 4; j++)
                wmma::load_matrix_sync(bf[j], Bs + (wn * 64 + j * 16) * LDT + ks * 16, LDT);
            #pragma unroll
            for (int i = 0; i < 4; i++)
                #pragma unroll
                for (int j = 0; j < 4; j++)
                    wmma::mma_sync(cf[i][j], af[i], bf[j], cf[i][j]);
        }

        if (++bufidx == 3) bufidx = 0;
    }

    // ---- epilogue: strip-staged, coalesced, fused bias ----
    __syncthreads();   // everyone done with smem tiles; reuse as staging
    float* stage = reinterpret_cast<float*>(smem) + warp_id * (17 * 64);

    const int row0 = m0 + wm * 64;
    const int col0 = n0 + wn * 64;

    #pragma unroll
    for (int i = 0; i < 4; i++) {
        #pragma unroll
        for (int j = 0; j < 4; j++)
            wmma::store_matrix_sync(stage + j * 16, cf[i][j], 68, wmma::mem_row_major);
        __syncwarp();
        #pragma unroll
        for (int q = 0; q < 8; q++) {
            int idx = q * 32 + lane;       // 0..255 float4s
            int r  = idx >> 4;
            int c4 = idx & 15;
            float4 v = *reinterpret_cast<const float4*>(stage + r * 68 + c4 * 4);
            const float4 bb = *reinterpret_cast<const float4*>(bias + col0 + c4 * 4);
            v.x += bb.x; v.y += bb.y; v.z += bb.z; v.w += bb.w;
            *reinterpret_cast<float4*>(
                out + (size_t)(row0 + i * 16 + r) * N_DIM + col0 + c4 * 4) = v;
        }
        __syncwarp();
    }
}

extern "C" void kernel_launch(void* const* d_in, const int* in_sizes, int n_in,
                              void* d_out, int out_size)
{
    const float* x      = (const float*)d_in[0];
    const int*   qw     = (const int*)d_in[1];
    const float* scales = (const float*)d_in[2];
    const float* bias   = (const float*)d_in[3];
    float* out = (float*)d_out;

    cudaFuncSetAttribute(gptq_gemm_kernel,
                         cudaFuncAttributeMaxDynamicSharedMemorySize, SMEM_TOTAL);

    // pre-pass 1: x fp32 -> fp16 permuted
    convert_x_kernel<<<(M_DIM * K_DIM) / 8 / 256, 256>>>(x);

    // pre-pass 2: W int4 -> fp16 permuted [N][K]
    {
        dim3 g(K_DIM / 64, N_DIM / 256);   // (64, 43)
        dequant_w_kernel<<<g, 256>>>(qw, scales);
    }

    dim3 grid(N_DIM / BN, M_DIM / BM);     // (86, 64)
    gptq_gemm_kernel<<<grid, NTHREADS, SMEM_TOTAL>>>(bias, out);
}

// round 13
// speedup vs baseline: 1.0607x; 1.0228x over previous
#include <cuda_runtime.h>
#include <cuda_fp16.h>
#include <mma.h>
#include <cstdint>

using namespace nvcuda;

// ---------------- problem constants ----------------
#define K_DIM 4096
#define N_DIM 11008
#define M_DIM 8192

// ---------------- tiling ----------------
#define BM 128
#define BN 128
#define BK 64
#define KT (K_DIM / BK)      // 64
#define NTHREADS 128         // 4 warps, 2x2 grid of 64x64 warp tiles
#define LDT 72               // padded smem stride in halves (144B rows)

// smem: 3 A buffers + 3 B buffers (triple-buffered, depth-2 in flight)
#define A_BYTES (BM * LDT * 2)      // 18432
#define B_BYTES (BN * LDT * 2)      // 18432
#define SMEM_TOTAL (3 * A_BYTES + 3 * B_BYTES)   // 110592 -> 2 CTAs/SM

// fp16 scratch, both with k-pair permutation [0,4,1,5,2,6,3,7] per 8-group
// (consistent permutation of both operands leaves the GEMM invariant;
//  fp32 x values are exact fp16 -> lossless)
__device__ __half g_xh[(size_t)M_DIM * K_DIM];
__device__ __half g_wh[(size_t)N_DIM * K_DIM];   // [N][K]

__device__ __forceinline__ uint32_t smem_u32(const void* p) {
    uint32_t a;
    asm("{ .reg .u64 t; cvta.to.shared.u64 t, %1; cvt.u32.u64 %0, t; }" : "=r"(a) : "l"(p));
    return a;
}
__device__ __forceinline__ void cp_async16(uint32_t dst, const void* src) {
    asm volatile("cp.async.cg.shared.global [%0], [%1], 16;" :: "r"(dst), "l"(src) : "memory");
}
__device__ __forceinline__ void cp_commit() {
    asm volatile("cp.async.commit_group;" ::: "memory");
}
__device__ __forceinline__ void cp_wait0() {
    asm volatile("cp.async.wait_group 0;" ::: "memory");
}
__device__ __forceinline__ void cp_wait1() {
    asm volatile("cp.async.wait_group 1;" ::: "memory");
}

// ---------------- pre-pass 1: x fp32 -> fp16, k-pair-permuted ----------------
// output order per 8-group: (f0,f4),(f1,f5),(f2,f6),(f3,f7)
__global__ __launch_bounds__(256) void convert_x_kernel(const float* __restrict__ x) {
    size_t i = (size_t)blockIdx.x * 256 + threadIdx.x;   // one uint4 (8 halves) per thread
    const float4* p = reinterpret_cast<const float4*>(x) + 2 * i;
    float4 a = p[0], b = p[1];   // a = k0..k3, b = k4..k7
    __half2 h[4];
    h[0] = __floats2half2_rn(a.x, b.x);
    h[1] = __floats2half2_rn(a.y, b.y);
    h[2] = __floats2half2_rn(a.z, b.z);
    h[3] = __floats2half2_rn(a.w, b.w);
    reinterpret_cast<uint4*>(g_xh)[i] = *reinterpret_cast<uint4*>(h);
}

// ---------------- pre-pass 2: dequant W -> fp16 [N][K], permuted ----------------
// grid (K/64, N/256), 256 threads; thread owns one n-column, 8 packed words
__global__ __launch_bounds__(256) void dequant_w_kernel(
    const int* __restrict__ qw, const float* __restrict__ scales)
{
    const int k0 = blockIdx.x * 64;
    const int n  = blockIdx.y * 256 + threadIdx.x;

    float sf = scales[(size_t)(k0 >> 7) * N_DIM + n];
    __half2 s2 = __half2half2(__float2half(sf));
    const __half2 c1032 = __floats2half2_rn(1032.0f, 1032.0f);

    const int* qp = qw + (size_t)(k0 >> 3) * N_DIM + n;
    uint4* wp = reinterpret_cast<uint4*>(g_wh + (size_t)n * K_DIM + k0);

    #pragma unroll
    for (int r = 0; r < 8; r++) {
        unsigned q = (unsigned)qp[(size_t)r * N_DIM];
        unsigned y0 = (q         & 0x000f000fu) | 0x64006400u;  // (k0,k4)+1024
        unsigned y1 = ((q >> 4)  & 0x000f000fu) | 0x64006400u;  // (k1,k5)+1024
        unsigned y2 = ((q >> 8)  & 0x000f000fu) | 0x64006400u;  // (k2,k6)+1024
        unsigned y3 = ((q >> 12) & 0x000f000fu) | 0x64006400u;  // (k3,k7)+1024
        __half2 v[4];
        v[0] = __hmul2(__hsub2(*reinterpret_cast<__half2*>(&y0), c1032), s2);
        v[1] = __hmul2(__hsub2(*reinterpret_cast<__half2*>(&y1), c1032), s2);
        v[2] = __hmul2(__hsub2(*reinterpret_cast<__half2*>(&y2), c1032), s2);
        v[3] = __hmul2(__hsub2(*reinterpret_cast<__half2*>(&y3), c1032), s2);
        wp[r] = *reinterpret_cast<uint4*>(v);   // 16B; thread writes 128B contiguous
    }
}

// ---------------- main GEMM (pure fp16, cp.async both operands) ----------------
// grid is (M/BM, N/BN): blockIdx.x = m-tile so concurrent waves span all m
// with only ~5 n-tiles -> W slice + x fit L2 (~73MB < 126MB), no thrash.
__global__ __launch_bounds__(NTHREADS, 2)
void gptq_gemm_kernel(const float* __restrict__ bias,
                      float*       __restrict__ out)
{
    extern __shared__ __align__(128) char smem[];
    const uint32_t sb = smem_u32(smem);

    const int tid     = threadIdx.x;
    const int warp_id = tid >> 5;
    const int lane    = tid & 31;
    const int m0 = blockIdx.x * BM;
    const int n0 = blockIdx.y * BN;

    // warp grid: 2 along M x 2 along N, each warp owns 64x64
    const int wm = warp_id & 1;
    const int wn = warp_id >> 1;

    wmma::fragment<wmma::accumulator, 16, 16, 16, float> cf[4][4];
    #pragma unroll
    for (int i = 0; i < 4; i++)
        #pragma unroll
        for (int j = 0; j < 4; j++)
            wmma::fill_fragment(cf[i][j], 0.0f);

    // issue one combined A+B tile copy (one commit group)
    auto cpAB = [&](int kt, int bufidx) {
        const int k0 = kt * BK;
        const uint32_t a_off = (uint32_t)(bufidx * A_BYTES);
        const uint32_t b_off = (uint32_t)(3 * A_BYTES + bufidx * B_BYTES);
        #pragma unroll
        for (int r = 0; r < 8; r++) {
            int idx = tid + NTHREADS * r;          // 0..1023
            int row = idx >> 3, c = idx & 7;
            cp_async16(sb + a_off + (uint32_t)(row * (LDT * 2) + c * 16),
                       g_xh + (size_t)(m0 + row) * K_DIM + k0 + c * 8);
        }
        #pragma unroll
        for (int r = 0; r < 8; r++) {
            int idx = tid + NTHREADS * r;          // 0..1023
            int row = idx >> 3, c = idx & 7;
            cp_async16(sb + b_off + (uint32_t)(row * (LDT * 2) + c * 16),
                       g_wh + (size_t)(n0 + row) * K_DIM + k0 + c * 8);
        }
        cp_commit();
    };

    // ---- prologue: tiles 0,1 in flight ----
    cpAB(0, 0);
    cpAB(1, 1);

    int bufidx = 0;  // kt % 3

    for (int kt = 0; kt < KT; kt++) {
        const uint32_t a_off = (uint32_t)(bufidx * A_BYTES);
        const uint32_t b_off = (uint32_t)(3 * A_BYTES + bufidx * B_BYTES);

        // tile kt resident (kt+1 may remain in flight)
        if (kt < KT - 1) cp_wait1(); else cp_wait0();
        __syncthreads();     // all warps done with MMA(kt-1) -> buffer (kt+2)%3 free

        if (kt + 2 < KT) {
            int nxt = bufidx + 2; if (nxt >= 3) nxt -= 3;
            cpAB(kt + 2, nxt);
        }

        // ---- pure tensor phase ----
        const __half* As = reinterpret_cast<const __half*>(smem + a_off);
        const __half* Bs = reinterpret_cast<const __half*>(smem + b_off);
        #pragma unroll
        for (int ks = 0; ks < BK / 16; ks++) {
            wmma::fragment<wmma::matrix_a, 16, 16, 16, __half, wmma::row_major> af[4];
            wmma::fragment<wmma::matrix_b, 16, 16, 16, __half, wmma::col_major> bf[4];
            #pragma unroll
            for (int i = 0; i < 4; i++)
                wmma::load_matrix_sync(af[i], As + (wm * 64 + i * 16) * LDT + ks * 16, LDT);
            #pragma unroll
            for (int j = 0; j < 4; j++)
                wmma::load_matrix_sync(bf[j], Bs + (wn * 64 + j * 16) * LDT + ks * 16, LDT);
            #pragma unroll
            for (int i = 0; i < 4; i++)
                #pragma unroll
                for (int j = 0; j < 4; j++)
                    wmma::mma_sync(cf[i][j], af[i], bf[j], cf[i][j]);
        }

        if (++bufidx == 3) bufidx = 0;
    }

    // ---- epilogue: strip-staged, coalesced, fused bias ----
    __syncthreads();   // everyone done with smem tiles; reuse as staging
    float* stage = reinterpret_cast<float*>(smem) + warp_id * (17 * 64);

    const int row0 = m0 + wm * 64;
    const int col0 = n0 + wn * 64;

    #pragma unroll
    for (int i = 0; i < 4; i++) {
        #pragma unroll
        for (int j = 0; j < 4; j++)
            wmma::store_matrix_sync(stage + j * 16, cf[i][j], 68, wmma::mem_row_major);
        __syncwarp();
        #pragma unroll
        for (int q = 0; q < 8; q++) {
            int idx = q * 32 + lane;       // 0..255 float4s
            int r  = idx >> 4;
            int c4 = idx & 15;
            float4 v = *reinterpret_cast<const float4*>(stage + r * 68 + c4 * 4);
            const float4 bb = *reinterpret_cast<const float4*>(bias + col0 + c4 * 4);
            v.x += bb.x; v.y += bb.y; v.z += bb.z; v.w += bb.w;
            *reinterpret_cast<float4*>(
                out + (size_t)(row0 + i * 16 + r) * N_DIM + col0 + c4 * 4) = v;
        }
        __syncwarp();
    }
}

extern "C" void kernel_launch(void* const* d_in, const int* in_sizes, int n_in,
                              void* d_out, int out_size)
{
    const float* x      = (const float*)d_in[0];
    const int*   qw     = (const int*)d_in[1];
    const float* scales = (const float*)d_in[2];
    const float* bias   = (const float*)d_in[3];
    float* out = (float*)d_out;

    cudaFuncSetAttribute(gptq_gemm_kernel,
                         cudaFuncAttributeMaxDynamicSharedMemorySize, SMEM_TOTAL);

    // pre-pass 1: x fp32 -> fp16 permuted
    convert_x_kernel<<<(M_DIM * K_DIM) / 8 / 256, 256>>>(x);

    // pre-pass 2: W int4 -> fp16 permuted [N][K]
    {
        dim3 g(K_DIM / 64, N_DIM / 256);   // (64, 43)
        dequant_w_kernel<<<g, 256>>>(qw, scales);
    }

    // m-major grid: concurrent waves span all m-tiles, few n-tiles -> L2-resident W
    dim3 grid(M_DIM / BM, N_DIM / BN);     // (64, 86)
    gptq_gemm_kernel<<<grid, NTHREADS, SMEM_TOTAL>>>(bias, out);
}